// round 3
// baseline (speedup 1.0000x reference)
#include <cuda_runtime.h>
#include <cstdint>

// Problem constants
#define N_ROWS 32768      // B*T = 8*4096
#define D      64
#define K      1024
#define TK     128        // K-tile staged in shared memory
#define BLK    128        // threads per block (1 thread = 1 row)
#define NBLK   (N_ROWS / BLK)   // 256 blocks

// Output layout (flattened tuple order: quantized, encodings, indices, loss)
#define OFF_QUANT 0
#define OFF_ENC   ((size_t)N_ROWS * D)                 // 2,097,152
#define OFF_IDX   (OFF_ENC + (size_t)N_ROWS * K)       // 35,651,584
#define OFF_LOSS  (OFF_IDX + (size_t)N_ROWS)           // 35,684,352

// Scratch (no cudaMalloc allowed)
__device__ float g_rowloss[N_ROWS];

// Packed fp32x2 helpers (sm_103a FFMA2 path — only reachable via PTX f32x2)
#define FMA2(acc, xa, eb) \
    asm("fma.rn.f32x2 %0, %1, %2, %0;" : "+l"(acc) : "l"(xa), "l"(eb))
#define UNPACK2(lo, hi, v) \
    asm("mov.b64 {%0, %1}, %2;" : "=f"(lo), "=f"(hi) : "l"(v))
#define PACK_DUP(dst, v) \
    asm("mov.b64 %0, {%1, %1};" : "=l"(dst) : "f"(v))

// ---------------------------------------------------------------------------
// Main kernel: per-row argmin of (||e_k||^2 - 2*x.e_k) via packed f32x2 FMA.
// Also writes quantized rows, indices, full one-hot encodings (zeros written
// cooperatively per tile, overlapped with compute), and per-row loss partials.
// ---------------------------------------------------------------------------
__global__ __launch_bounds__(BLK, 2) void vq_main(const float* __restrict__ x,
                                                  const float* __restrict__ emb,
                                                  float* __restrict__ out) {
    __shared__ __align__(16) float es[D * TK];   // 32 KB: emb K-tile, [d][kt]
    __shared__ float esq_s[TK];                  // 512 B: ||e||^2 for the tile

    const int tid = threadIdx.x;
    const int row = blockIdx.x * BLK + tid;
    const int warp = tid >> 5, lane = tid & 31;

    // Load this thread's x row; keep only the duplicated-packed form (v,v).
    unsigned long long xp[D];   // 128 regs
    {
        const float4* xpin = (const float4*)(x + (size_t)row * D);
        #pragma unroll
        for (int i = 0; i < D / 4; i++) {
            float4 v = xpin[i];
            PACK_DUP(xp[i * 4 + 0], v.x);
            PACK_DUP(xp[i * 4 + 1], v.y);
            PACK_DUP(xp[i * 4 + 2], v.z);
            PACK_DUP(xp[i * 4 + 3], v.w);
        }
    }

    float best = 3.4e38f;
    int   bi   = 0;

    for (int t = 0; t < K / TK; t++) {
        __syncthreads();  // protect smem reuse across tiles
        // Stage embeddings tile [D x TK]: coalesced float4 loads (16/thread).
        const float* embt = emb + t * TK;
        #pragma unroll
        for (int i = 0; i < (D * TK / 4) / BLK; i++) {
            int j  = i * BLK + tid;       // float4 index
            int e0 = j * 4;
            int d  = e0 / TK;
            int kt = e0 % TK;
            *(float4*)(es + d * TK + kt) =
                *(const float4*)(embt + (size_t)d * K + kt);
        }
        __syncthreads();

        // Per-tile ||e_k||^2 from the staged tile (conflict-free LDS).
        {
            float eq = 0.f;
            #pragma unroll
            for (int d = 0; d < D; d++) {
                float e = es[d * TK + tid];
                eq = fmaf(e, e, eq);
            }
            esq_s[tid] = eq;
        }

        // Cooperative zero-fill of this tile's encodings columns (coalesced,
        // independent gmem traffic — drains under the compute below).
        {
            float4 z = make_float4(0.f, 0.f, 0.f, 0.f);
            float* encbase = out + OFF_ENC
                           + (size_t)(blockIdx.x * BLK) * K + (size_t)t * TK;
            #pragma unroll
            for (int rr = warp; rr < BLK; rr += BLK / 32) {
                *(float4*)(encbase + (size_t)rr * K + lane * 4) = z;
            }
        }
        __syncthreads();  // esq_s ready for all threads

        // Scan tile: 8 codewords per group, packed f32x2 FMA (FFMA2).
        #pragma unroll 1
        for (int kk = 0; kk < TK; kk += 8) {
            unsigned long long a0 = 0ull, a1 = 0ull, a2 = 0ull, a3 = 0ull;
            #pragma unroll
            for (int d = 0; d < D; d++) {
                const ulonglong2* ep = (const ulonglong2*)(es + d * TK + kk);
                ulonglong2 e0 = ep[0];   // k: kk..kk+3
                ulonglong2 e1 = ep[1];   // k: kk+4..kk+7
                FMA2(a0, xp[d], e0.x);
                FMA2(a1, xp[d], e0.y);
                FMA2(a2, xp[d], e1.x);
                FMA2(a3, xp[d], e1.y);
            }
            float s0, s1, s2, s3, s4, s5, s6, s7;
            UNPACK2(s0, s1, a0);
            UNPACK2(s2, s3, a1);
            UNPACK2(s4, s5, a2);
            UNPACK2(s6, s7, a3);
            // score = ||e||^2 - 2*sim (argmin-equivalent to full distance)
            float c0 = fmaf(-2.f, s0, esq_s[kk + 0]);
            float c1 = fmaf(-2.f, s1, esq_s[kk + 1]);
            float c2 = fmaf(-2.f, s2, esq_s[kk + 2]);
            float c3 = fmaf(-2.f, s3, esq_s[kk + 3]);
            float c4 = fmaf(-2.f, s4, esq_s[kk + 4]);
            float c5 = fmaf(-2.f, s5, esq_s[kk + 5]);
            float c6 = fmaf(-2.f, s6, esq_s[kk + 6]);
            float c7 = fmaf(-2.f, s7, esq_s[kk + 7]);
            int kb = t * TK + kk;
            // strict < in index order => first-min tie-break (jnp.argmax)
            if (c0 < best) { best = c0; bi = kb + 0; }
            if (c1 < best) { best = c1; bi = kb + 1; }
            if (c2 < best) { best = c2; bi = kb + 2; }
            if (c3 < best) { best = c3; bi = kb + 3; }
            if (c4 < best) { best = c4; bi = kb + 4; }
            if (c5 < best) { best = c5; bi = kb + 5; }
            if (c6 < best) { best = c6; bi = kb + 6; }
            if (c7 < best) { best = c7; bi = kb + 7; }
        }
    }

    // All cooperative zero-fills done before anyone scatters a 1.0.
    __syncthreads();

    // quantized row (gather codeword column) + exact per-row loss partial
    float ls = 0.f;
    const float* ecol = emb + bi;                  // stride K down column
    float* q = out + OFF_QUANT + (size_t)row * D;
    #pragma unroll
    for (int d = 0; d < D; d++) {
        float e = ecol[(size_t)d * K];
        q[d] = e;
        float xv;
        {   // low half of packed (v,v) is v
            float hi_unused;
            UNPACK2(xv, hi_unused, xp[d]);
        }
        float df = e - xv;
        ls = fmaf(df, df, ls);
    }
    g_rowloss[row] = ls;

    // index (cast to float; exact for < 2^24)
    out[OFF_IDX + row] = (float)bi;

    // one-hot scatter into the zeros this block just wrote
    out[OFF_ENC + (size_t)row * K + bi] = 1.0f;
}

// ---------------------------------------------------------------------------
// Deterministic loss reduction: fixed-order strided partials + smem tree.
// ---------------------------------------------------------------------------
__global__ void loss_kernel(float* __restrict__ out) {
    __shared__ double sb[1024];
    int tid = threadIdx.x;
    double s = 0.0;
    for (int i = tid; i < N_ROWS; i += 1024) s += (double)g_rowloss[i];
    sb[tid] = s;
    __syncthreads();
    for (int off = 512; off > 0; off >>= 1) {
        if (tid < off) sb[tid] += sb[tid + off];
        __syncthreads();
    }
    if (tid == 0) {
        out[OFF_LOSS] = (float)(sb[0] / (double)((size_t)N_ROWS * D));
    }
}

// ---------------------------------------------------------------------------
extern "C" void kernel_launch(void* const* d_in, const int* in_sizes, int n_in,
                              void* d_out, int out_size) {
    const float* x   = (const float*)d_in[0];   // [B,T,D] = [8,4096,64]
    const float* emb = (const float*)d_in[1];   // [D,K]   = [64,1024]
    float* out = (float*)d_out;

    vq_main<<<NBLK, BLK>>>(x, emb, out);
    loss_kernel<<<1, 1024>>>(out);
}

// round 5
// speedup vs baseline: 1.4609x; 1.4609x over previous
#include <cuda_runtime.h>
#include <cstdint>

#define N_ROWS 32768
#define D      64
#define K      1024
#define BLK    128
#define NBLK   (N_ROWS / BLK)          // 256 CTAs
#define NCH    64                      // codewords per chunk
#define NCHUNK (K / NCH)               // 16

#define OFF_QUANT 0
#define OFF_ENC   ((size_t)N_ROWS * D)
#define OFF_IDX   (OFF_ENC + (size_t)N_ROWS * K)
#define OFF_LOSS  (OFF_IDX + (size_t)N_ROWS)

// shared memory layout (floats): esq[1024] | buf0[8192] | buf1[8192] | xlo[128*68]
#define SMF_ESQ  0
#define SMF_BUF  1024
#define SMF_XLO  (1024 + 16384)
#define XSTRIDE  68                              // 4*68 % 16 == 0, conflict-free frags
#define SMEM_FLOATS (SMF_XLO + 128 * XSTRIDE)
#define SMEM_SZ  (SMEM_FLOATS * 4)               // 104448 B -> 2 CTAs/SM

// fragment-packed codebook: [tile(128)][ks(8)][lane(32)][j(2)]
__device__ float g_bh[K / 8 * 8 * 64];   // 65536 floats, tf32-hi
__device__ float g_bl[K / 8 * 8 * 64];   // tf32-lo
__device__ float g_et [K * D];           // exact emb^T [k][d]
__device__ float g_esq[K];
__device__ unsigned long long g_loss;

__device__ __forceinline__ uint32_t smem_u32(const void* p) {
    uint32_t a;
    asm("{ .reg .u64 t; cvta.to.shared.u64 t, %1; cvt.u32.u64 %0, t; }"
        : "=r"(a) : "l"(p));
    return a;
}
__device__ __forceinline__ float tf32_rna(float v) {
    uint32_t u;
    asm("cvt.rna.tf32.f32 %0, %1;" : "=r"(u) : "f"(v));
    return __uint_as_float(u);
}

#define CP16(dst, src) asm volatile( \
    "cp.async.cg.shared.global [%0], [%1], 16;" :: "r"(dst), "l"(src) : "memory")
#define CP_COMMIT() asm volatile("cp.async.commit_group;" ::: "memory")
#define CP_WAIT(n)  asm volatile("cp.async.wait_group %0;" :: "n"(n) : "memory")

#define LDS64(r0, r1, addr) asm volatile( \
    "ld.shared.v2.b32 {%0,%1}, [%2];" : "=r"(r0), "=r"(r1) : "r"(addr))

// m16n8k8 tf32 mma (sm_80+ baseline PTX -> compiles for plain sm_103 target)
#define MMA8(Cp, Ap, b0, b1) asm volatile( \
    "mma.sync.aligned.m16n8k8.row.col.f32.tf32.tf32.f32 " \
    "{%0,%1,%2,%3},{%4,%5,%6,%7},{%8,%9},{%0,%1,%2,%3};" \
    : "+f"((Cp)[0]), "+f"((Cp)[1]), "+f"((Cp)[2]), "+f"((Cp)[3]) \
    : "r"((Ap)[0]), "r"((Ap)[1]), "r"((Ap)[2]), "r"((Ap)[3]), \
      "r"(b0), "r"(b1))

// ---------------- prep: exact e^T, ||e||^2, fragment-packed tf32 splits ----
__global__ void prep_et(const float* __restrict__ emb) {
    int k = blockIdx.x * blockDim.x + threadIdx.x;
    if (k == 0) g_loss = 0ull;
    if (k >= K) return;
    float s = 0.f;
    #pragma unroll
    for (int d = 0; d < D; d++) {
        float v = emb[d * K + k];
        g_et[k * D + d] = v;
        s = fmaf(v, v, s);
    }
    g_esq[k] = s;
}

// one thread per (tile, ks, lane) slot; writes the 2 B-frag values (hi & lo)
__global__ void prep_frag(const float* __restrict__ emb) {
    int idx = blockIdx.x * blockDim.x + threadIdx.x;   // 0 .. 32767
    if (idx >= 128 * 8 * 32) return;
    int lane = idx & 31;
    int ks   = (idx >> 5) & 7;
    int t    = idx >> 8;
    int cw   = t * 8 + (lane >> 2);
    #pragma unroll
    for (int j = 0; j < 2; j++) {
        int d = ks * 8 + (lane & 3) + 4 * j;
        float v = emb[d * K + cw];
        float h = tf32_rna(v);
        g_bh[idx * 2 + j] = h;
        g_bl[idx * 2 + j] = tf32_rna(v - h);
    }
}

// ---------------- staging: linear 16KB+16KB copy of one chunk -------------
__device__ __forceinline__ void stage_chunk(uint32_t bufb, int c, int tid) {
    const char* sh = (const char*)(g_bh + (size_t)c * 4096);
    const char* sl = (const char*)(g_bl + (size_t)c * 4096);
    #pragma unroll
    for (int i = 0; i < 8; i++) {
        uint32_t o = (uint32_t)(i * BLK + tid) * 16;
        CP16(bufb + o, sh + o);
        CP16(bufb + 16384 + o, sl + o);
    }
    CP_COMMIT();
}

// lexicographic (score, index) less-than: mirrors "first argmin" tie-break
__device__ __forceinline__ bool sless(float s, int i, float S, int I) {
    return (s < S) || (s == S && i < I);
}

// ---------------- main ----------------------------------------------------
__global__ __launch_bounds__(BLK, 2) void vq_mma(const float* __restrict__ x,
                                                 float* __restrict__ out) {
    extern __shared__ __align__(16) float smem[];
    const uint32_t smb = smem_u32(smem);
    float* esq_s = smem + SMF_ESQ;
    float* xlo   = smem + SMF_XLO;
    const int tid  = threadIdx.x;
    const int wid  = tid >> 5, lane = tid & 31;
    const int r0   = lane >> 2, c0 = lane & 3;
    const int rowbase = blockIdx.x * BLK;

    // start B chunk 0 transfer immediately
    stage_chunk(smb + (SMF_BUF) * 4, 0, tid);

    // esq -> smem
    #pragma unroll
    for (int i = 0; i < K / BLK; i++)
        esq_s[i * BLK + tid] = g_esq[i * BLK + tid];

    // stage raw x tile into xlo region (stride 68, 16B-aligned rows)
    {
        const float4* xs = (const float4*)(x + (size_t)rowbase * D);
        #pragma unroll
        for (int i = 0; i < 16; i++) {
            int idx = i * BLK + tid;           // float4 slot
            int r = idx >> 4, d4 = idx & 15;
            *(float4*)(xlo + r * XSTRIDE + d4 * 4) = xs[idx];
        }
    }
    __syncthreads();

    // build A_hi fragments in registers; overwrite xlo in place with tf32-lo.
    // per-warp bijective (each (r,d) touched by exactly one lane/slot).
    uint32_t ahi[64];
    #pragma unroll
    for (int mt = 0; mt < 2; mt++)
      #pragma unroll
      for (int ks = 0; ks < 8; ks++)
        #pragma unroll
        for (int q = 0; q < 4; q++) {
            int r = wid * 32 + mt * 16 + r0 + 8 * (q & 1);
            int d = ks * 8 + c0 + 4 * (q >> 1);
            float* p = xlo + r * XSTRIDE + d;
            float v = *p;
            float h = tf32_rna(v);
            ahi[(mt * 8 + ks) * 4 + q] = __float_as_uint(h);
            *p = tf32_rna(v - h);
        }
    __syncthreads();

    // per-thread top-2 per row-slot: slot = mt*2 + (c-reg>>1)
    float s1[4], s2[4];
    int   i1[4], i2[4];
    #pragma unroll
    for (int s = 0; s < 4; s++) { s1[s] = s2[s] = 3.4e38f; i1[s] = i2[s] = 0; }

    #pragma unroll 1
    for (int c = 0; c < NCHUNK; c++) {
        if (c + 1 < NCHUNK) {
            stage_chunk(smb + (SMF_BUF + ((c + 1) & 1) * 8192) * 4, c + 1, tid);
            CP_WAIT(1);
        } else {
            CP_WAIT(0);
        }
        __syncthreads();   // buf[c] visible everywhere

        // encodings zero-fill for this chunk's 64 columns (hides latency)
        {
            float4 z = make_float4(0.f, 0.f, 0.f, 0.f);
            float* enc = out + OFF_ENC + (size_t)rowbase * K + (size_t)c * NCH;
            #pragma unroll
            for (int j = 0; j < 16; j++) {
                int idx = j * BLK + tid;
                *(float4*)(enc + (size_t)(idx >> 4) * K + (idx & 15) * 4) = z;
            }
        }

        const uint32_t bufb = smb + (SMF_BUF + (c & 1) * 8192) * 4;

        #pragma unroll
        for (int ng = 0; ng < 2; ng++) {
            float C[2][4][4];
            #pragma unroll
            for (int mt = 0; mt < 2; mt++)
                #pragma unroll
                for (int nt = 0; nt < 4; nt++)
                    #pragma unroll
                    for (int q = 0; q < 4; q++) C[mt][nt][q] = 0.f;

            #pragma unroll
            for (int ks = 0; ks < 8; ks++) {
                uint32_t bh0[4], bh1[4], bl0[4], bl1[4];
                #pragma unroll
                for (int nt = 0; nt < 4; nt++) {
                    uint32_t a = bufb +
                        (uint32_t)((((ng * 4 + nt) * 8 + ks) * 64 + lane * 2) * 4);
                    LDS64(bh0[nt], bh1[nt], a);
                    LDS64(bl0[nt], bl1[nt], a + 16384);
                }
                #pragma unroll
                for (int mt = 0; mt < 2; mt++) {
                    // A_lo fragment from smem (conflict-free: (4r+d)%32 distinct)
                    uint32_t al[4];
                    #pragma unroll
                    for (int q = 0; q < 4; q++)
                        al[q] = __float_as_uint(
                            xlo[(wid * 32 + mt * 16 + r0 + 8 * (q & 1)) * XSTRIDE
                                + ks * 8 + c0 + 4 * (q >> 1)]);
                    const uint32_t* ah = ahi + (mt * 8 + ks) * 4;
                    #pragma unroll
                    for (int nt = 0; nt < 4; nt++) {
                        MMA8(C[mt][nt], ah, bh0[nt], bh1[nt]);  // hi*hi
                        MMA8(C[mt][nt], ah, bl0[nt], bl1[nt]);  // hi*lo
                        MMA8(C[mt][nt], al, bh0[nt], bh1[nt]);  // lo*hi
                    }
                }
            }

            // epilogue: scores + per-slot top-2 (cols ascending => first-wins)
            #pragma unroll
            for (int mt = 0; mt < 2; mt++)
                #pragma unroll
                for (int nt = 0; nt < 4; nt++)
                    #pragma unroll
                    for (int q = 0; q < 4; q++) {
                        int col = c * NCH + (ng * 4 + nt) * 8 + 2 * c0 + (q & 1);
                        float sc = fmaf(-2.f, C[mt][nt][q], esq_s[col]);
                        int sl = mt * 2 + (q >> 1);
                        if (sc < s1[sl]) {
                            s2[sl] = s1[sl]; i2[sl] = i1[sl];
                            s1[sl] = sc;     i1[sl] = col;
                        } else if (sc < s2[sl]) {
                            s2[sl] = sc; i2[sl] = col;
                        }
                    }
        }
        __syncthreads();   // all reads of buf[c] done before it is re-staged
    }

    // quad-merge top-2 across the 4 lanes sharing each row
    #pragma unroll
    for (int sl = 0; sl < 4; sl++) {
        #pragma unroll
        for (int off = 1; off <= 2; off <<= 1) {
            float os1 = __shfl_xor_sync(0xFFFFFFFF, s1[sl], off);
            int   oi1 = __shfl_xor_sync(0xFFFFFFFF, i1[sl], off);
            float os2 = __shfl_xor_sync(0xFFFFFFFF, s2[sl], off);
            int   oi2 = __shfl_xor_sync(0xFFFFFFFF, i2[sl], off);
            if (sless(os1, oi1, s1[sl], i1[sl])) {
                if (sless(s1[sl], i1[sl], os2, oi2)) {
                    s2[sl] = s1[sl]; i2[sl] = i1[sl];
                } else {
                    s2[sl] = os2; i2[sl] = oi2;
                }
                s1[sl] = os1; i1[sl] = oi1;
            } else if (sless(os1, oi1, s2[sl], i2[sl])) {
                s2[sl] = os1; i2[sl] = oi1;
            }
        }
    }
    // lane%4==0 holds final per-row top-2; publish to smem row table
    int2* rowtab = (int2*)(smem + SMF_BUF);
    if (c0 == 0) {
        #pragma unroll
        for (int sl = 0; sl < 4; sl++) {
            int rloc = wid * 32 + (sl >> 1) * 16 + (sl & 1) * 8 + r0;
            rowtab[rloc] = make_int2(i1[sl], i2[sl]);
        }
    }
    __syncthreads();

    // final per-row epilogue: exact fp32 rescore of top-2, outputs, loss
    const int row = rowbase + tid;
    int ca = rowtab[tid].x, cb = rowtab[tid].y;
    float xr[D];
    {
        const float4* xp = (const float4*)(x + (size_t)row * D);
        #pragma unroll
        for (int i = 0; i < D / 4; i++) {
            float4 v = xp[i];
            xr[4*i] = v.x; xr[4*i+1] = v.y; xr[4*i+2] = v.z; xr[4*i+3] = v.w;
        }
    }
    float da = 0.f, db = 0.f;
    {
        const float* ea = g_et + (size_t)ca * D;
        const float* eb = g_et + (size_t)cb * D;
        #pragma unroll
        for (int d = 0; d < D; d++) {
            da = fmaf(xr[d], ea[d], da);
            db = fmaf(xr[d], eb[d], db);
        }
    }
    float sa = fmaf(-2.f, da, esq_s[ca]);
    float sb = fmaf(-2.f, db, esq_s[cb]);
    int bi = sless(sb, cb, sa, ca) ? cb : ca;

    float ls = 0.f;
    {
        const float4* ep = (const float4*)(g_et + (size_t)bi * D);
        float4* qp = (float4*)(out + OFF_QUANT + (size_t)row * D);
        #pragma unroll
        for (int i = 0; i < D / 4; i++) {
            float4 e = ep[i];
            qp[i] = e;
            float d0 = e.x - xr[4*i],   d1 = e.y - xr[4*i+1];
            float d2 = e.z - xr[4*i+2], d3 = e.w - xr[4*i+3];
            ls = fmaf(d0, d0, ls); ls = fmaf(d1, d1, ls);
            ls = fmaf(d2, d2, ls); ls = fmaf(d3, d3, ls);
        }
    }
    #pragma unroll
    for (int off = 16; off > 0; off >>= 1)
        ls += __shfl_xor_sync(0xFFFFFFFF, ls, off);
    if (lane == 0)   // fixed-point accumulate: order-independent => deterministic
        atomicAdd(&g_loss, (unsigned long long)__float2ll_rn(ls * 16777216.0f));

    out[OFF_IDX + row] = (float)bi;
    out[OFF_ENC + (size_t)row * K + bi] = 1.0f;
}

__global__ void loss_finalize(float* __restrict__ out) {
    out[OFF_LOSS] = (float)((double)g_loss
                  / (16777216.0 * (double)N_ROWS * (double)D));
}

extern "C" void kernel_launch(void* const* d_in, const int* in_sizes, int n_in,
                              void* d_out, int out_size) {
    const float* x   = (const float*)d_in[0];   // [8,4096,64]
    const float* emb = (const float*)d_in[1];   // [64,1024]
    float* out = (float*)d_out;

    cudaFuncSetAttribute(vq_mma, cudaFuncAttributeMaxDynamicSharedMemorySize,
                         SMEM_SZ);
    prep_et<<<(K + 255) / 256, 256>>>(emb);
    prep_frag<<<128, 256>>>(emb);
    vq_mma<<<NBLK, BLK, SMEM_SZ>>>(x, out);
    loss_finalize<<<1, 1>>>(out);
}

// round 6
// speedup vs baseline: 1.7993x; 1.2317x over previous
#include <cuda_runtime.h>
#include <cuda_fp16.h>
#include <cstdint>

#define N_ROWS 32768
#define D      64
#define K      1024
#define BLK    128
#define NBLK   (N_ROWS / BLK)          // 256 CTAs
#define NCH    64                      // codewords per chunk
#define NCHUNK (K / NCH)               // 16

#define OFF_QUANT 0
#define OFF_ENC   ((size_t)N_ROWS * D)
#define OFF_IDX   (OFF_ENC + (size_t)N_ROWS * K)
#define OFF_LOSS  (OFF_IDX + (size_t)N_ROWS)

// smem (floats): esq[1024] | buf0[4096] | buf1[4096] | xtile[128*68]
#define SMF_ESQ  0
#define SMF_BUF  1024
#define SMF_X    (1024 + 8192)
#define XSTRIDE  68
#define SMEM_SZ  ((SMF_X + 128 * XSTRIDE) * 4)   // 71680 B -> 2 CTAs/SM

// fragment-packed codebook, fp16 2-term split.
// index: [nt_global(128)][ks(4)][lane(32)] -> uint2 {h2(d0,d0+1), h2(d0+8,d0+9)}
__device__ uint2 g_b0[128 * 4 * 32];
__device__ uint2 g_b1[128 * 4 * 32];
__device__ float g_et [K * D];           // exact emb^T [k][d]
__device__ float g_esq[K];
__device__ unsigned long long g_loss;

__device__ __forceinline__ uint32_t smem_u32(const void* p) {
    uint32_t a;
    asm("{ .reg .u64 t; cvta.to.shared.u64 t, %1; cvt.u32.u64 %0, t; }"
        : "=r"(a) : "l"(p));
    return a;
}
__device__ __forceinline__ uint32_t packh2(float a, float b) {
    __half2 h = __floats2half2_rn(a, b);   // a -> low (smaller k index)
    return *(uint32_t*)&h;
}

#define CP16(dst, src) asm volatile( \
    "cp.async.cg.shared.global [%0], [%1], 16;" :: "r"(dst), "l"(src) : "memory")
#define CP_COMMIT() asm volatile("cp.async.commit_group;" ::: "memory")
#define CP_WAIT(n)  asm volatile("cp.async.wait_group %0;" :: "n"(n) : "memory")

#define LDS64(r0, r1, addr) asm volatile( \
    "ld.shared.v2.b32 {%0,%1}, [%2];" : "=r"(r0), "=r"(r1) : "r"(addr))

// m16n8k16 fp16 mma, f32 accumulate (sm_80+ baseline PTX)
#define MMAF16(Cp, Ap, B0, B1) asm volatile( \
    "mma.sync.aligned.m16n8k16.row.col.f32.f16.f16.f32 " \
    "{%0,%1,%2,%3},{%4,%5,%6,%7},{%8,%9},{%0,%1,%2,%3};" \
    : "+f"((Cp)[0]), "+f"((Cp)[1]), "+f"((Cp)[2]), "+f"((Cp)[3]) \
    : "r"((Ap)[0]), "r"((Ap)[1]), "r"((Ap)[2]), "r"((Ap)[3]), \
      "r"(B0), "r"(B1))

// ---------------- prep: exact e^T + ||e||^2 --------------------------------
__global__ void prep_et(const float* __restrict__ emb) {
    int k = blockIdx.x * blockDim.x + threadIdx.x;
    if (k == 0) g_loss = 0ull;
    if (k >= K) return;
    float s = 0.f;
    #pragma unroll
    for (int d = 0; d < D; d++) {
        float v = emb[d * K + k];
        g_et[k * D + d] = v;
        s = fmaf(v, v, s);
    }
    g_esq[k] = s;
}

// ---------------- prep: fp16 2-term fragment packing -----------------------
__global__ void prep_frag(const float* __restrict__ emb) {
    int idx = blockIdx.x * blockDim.x + threadIdx.x;   // 0..16383
    if (idx >= 128 * 4 * 32) return;
    int lane = idx & 31;
    int ks   = (idx >> 5) & 3;
    int nt   = idx >> 7;
    int cw   = nt * 8 + (lane >> 2);
    int d0   = ks * 16 + (lane & 3) * 2;

    float v[4];
    v[0] = emb[(d0    ) * K + cw];
    v[1] = emb[(d0 + 1) * K + cw];
    v[2] = emb[(d0 + 8) * K + cw];
    v[3] = emb[(d0 + 9) * K + cw];
    float h0[4], h1[4];
    #pragma unroll
    for (int j = 0; j < 4; j++) {
        h0[j] = __half2float(__float2half_rn(v[j]));
        h1[j] = v[j] - h0[j];
    }
    g_b0[idx] = make_uint2(packh2(h0[0], h0[1]), packh2(h0[2], h0[3]));
    g_b1[idx] = make_uint2(packh2(h1[0], h1[1]), packh2(h1[2], h1[3]));
}

// ---------------- staging: 8KB + 8KB linear copy per chunk -----------------
__device__ __forceinline__ void stage_chunk(uint32_t bufb, int c, int tid) {
    const char* s0 = (const char*)(g_b0 + (size_t)c * 1024);
    const char* s1 = (const char*)(g_b1 + (size_t)c * 1024);
    #pragma unroll
    for (int i = 0; i < 4; i++) {
        uint32_t o = (uint32_t)(i * BLK + tid) * 16;
        CP16(bufb + o,        s0 + o);
        CP16(bufb + 8192 + o, s1 + o);
    }
    CP_COMMIT();
}

__device__ __forceinline__ bool sless(float s, int i, float S, int I) {
    return (s < S) || (s == S && i < I);
}

// ---------------- main ------------------------------------------------------
__global__ __launch_bounds__(BLK, 2) void vq_mma(const float* __restrict__ x,
                                                 float* __restrict__ out) {
    extern __shared__ __align__(16) float smem[];
    const uint32_t smb = smem_u32(smem);
    float* esq_s = smem + SMF_ESQ;
    float* xs    = smem + SMF_X;
    const int tid  = threadIdx.x;
    const int wid  = tid >> 5, lane = tid & 31;
    const int r0   = lane >> 2, c0 = lane & 3;
    const int rowbase = blockIdx.x * BLK;

    stage_chunk(smb + SMF_BUF * 4, 0, tid);

    #pragma unroll
    for (int i = 0; i < K / BLK; i++)
        esq_s[i * BLK + tid] = g_esq[i * BLK + tid];

    // stage x tile (raw floats, stride 68)
    {
        const float4* xg = (const float4*)(x + (size_t)rowbase * D);
        #pragma unroll
        for (int i = 0; i < 16; i++) {
            int idx = i * BLK + tid;
            int r = idx >> 4, d4 = idx & 15;
            *(float4*)(xs + r * XSTRIDE + d4 * 4) = xg[idx];
        }
    }
    __syncthreads();

    // build A fragments in registers: y = -2x, split y = y0 + y1 (fp16)
    // slot = (mt*4 + ks)*4 + p ; p: bit0 = row+8, bit1 = k+8
    uint32_t ay0[32], ay1[32];
    #pragma unroll
    for (int mt = 0; mt < 2; mt++)
      #pragma unroll
      for (int ks = 0; ks < 4; ks++)
        #pragma unroll
        for (int p = 0; p < 4; p++) {
            int r = wid * 32 + mt * 16 + r0 + (p & 1) * 8;
            int d = ks * 16 + c0 * 2 + (p >> 1) * 8;
            float va = -2.f * xs[r * XSTRIDE + d];
            float vb = -2.f * xs[r * XSTRIDE + d + 1];
            float ha = __half2float(__float2half_rn(va));
            float hb = __half2float(__float2half_rn(vb));
            ay0[(mt * 4 + ks) * 4 + p] = packh2(ha, hb);
            ay1[(mt * 4 + ks) * 4 + p] = packh2(va - ha, vb - hb);
        }

    float s1[4], s2[4];
    int   i1[4], i2[4];
    #pragma unroll
    for (int s = 0; s < 4; s++) { s1[s] = s2[s] = 3.4e38f; i1[s] = i2[s] = 0; }

    #pragma unroll 1
    for (int c = 0; c < NCHUNK; c++) {
        if (c + 1 < NCHUNK) {
            stage_chunk(smb + (SMF_BUF + ((c + 1) & 1) * 4096) * 4, c + 1, tid);
            CP_WAIT(1);
        } else {
            CP_WAIT(0);
        }
        __syncthreads();   // buf[c] visible

        // encodings zero-fill for this chunk's 64 columns (hides latency)
        {
            float4 z = make_float4(0.f, 0.f, 0.f, 0.f);
            float* enc = out + OFF_ENC + (size_t)rowbase * K + (size_t)c * NCH;
            #pragma unroll
            for (int j = 0; j < 16; j++) {
                int idx = j * BLK + tid;
                *(float4*)(enc + (size_t)(idx >> 4) * K + (idx & 15) * 4) = z;
            }
        }

        const uint32_t bufb = smb + (SMF_BUF + (c & 1) * 4096) * 4;

        float C[2][8][4];
        #pragma unroll
        for (int mt = 0; mt < 2; mt++)
            #pragma unroll
            for (int nt = 0; nt < 8; nt++)
                #pragma unroll
                for (int q = 0; q < 4; q++) C[mt][nt][q] = 0.f;

        #pragma unroll
        for (int ks = 0; ks < 4; ks++) {
            uint32_t b0a[8], b0b[8], b1a[8], b1b[8];
            #pragma unroll
            for (int nt = 0; nt < 8; nt++) {
                uint32_t a = bufb + (uint32_t)(((nt * 4 + ks) * 32 + lane) * 8);
                LDS64(b0a[nt], b0b[nt], a);
                LDS64(b1a[nt], b1b[nt], a + 8192);
            }
            #pragma unroll
            for (int mt = 0; mt < 2; mt++) {
                const uint32_t* a0 = ay0 + (mt * 4 + ks) * 4;
                const uint32_t* a1 = ay1 + (mt * 4 + ks) * 4;
                #pragma unroll
                for (int nt = 0; nt < 8; nt++) {
                    MMAF16(C[mt][nt], a0, b0a[nt], b0b[nt]);  // y0*e0
                    MMAF16(C[mt][nt], a0, b1a[nt], b1b[nt]);  // y0*e1
                    MMAF16(C[mt][nt], a1, b0a[nt], b0b[nt]);  // y1*e0
                }
            }
        }

        // epilogue: sc = C + ||e||^2 ; per-slot top-2, cols ascending
        #pragma unroll
        for (int mt = 0; mt < 2; mt++)
            #pragma unroll
            for (int nt = 0; nt < 8; nt++)
                #pragma unroll
                for (int q = 0; q < 4; q++) {
                    int col = c * NCH + nt * 8 + c0 * 2 + (q & 1);
                    float sc = C[mt][nt][q] + esq_s[col];
                    int sl = mt * 2 + (q >> 1);
                    if (sc < s1[sl]) {
                        s2[sl] = s1[sl]; i2[sl] = i1[sl];
                        s1[sl] = sc;     i1[sl] = col;
                    } else if (sc < s2[sl]) {
                        s2[sl] = sc; i2[sl] = col;
                    }
                }
        __syncthreads();   // buf[c] reads done before restage
    }

    // quad-merge top-2 across the 4 lanes sharing each row
    #pragma unroll
    for (int sl = 0; sl < 4; sl++) {
        #pragma unroll
        for (int off = 1; off <= 2; off <<= 1) {
            float os1 = __shfl_xor_sync(0xFFFFFFFF, s1[sl], off);
            int   oi1 = __shfl_xor_sync(0xFFFFFFFF, i1[sl], off);
            float os2 = __shfl_xor_sync(0xFFFFFFFF, s2[sl], off);
            int   oi2 = __shfl_xor_sync(0xFFFFFFFF, i2[sl], off);
            if (sless(os1, oi1, s1[sl], i1[sl])) {
                if (sless(s1[sl], i1[sl], os2, oi2)) {
                    s2[sl] = s1[sl]; i2[sl] = i1[sl];
                } else {
                    s2[sl] = os2; i2[sl] = oi2;
                }
                s1[sl] = os1; i1[sl] = oi1;
            } else if (sless(os1, oi1, s2[sl], i2[sl])) {
                s2[sl] = os1; i2[sl] = oi1;
            }
        }
    }
    int2* rowtab = (int2*)(smem + SMF_BUF);
    if (c0 == 0) {
        #pragma unroll
        for (int sl = 0; sl < 4; sl++) {
            int rloc = wid * 32 + (sl >> 1) * 16 + (sl & 1) * 8 + r0;
            rowtab[rloc] = make_int2(i1[sl], i2[sl]);
        }
    }
    __syncthreads();

    // final per-row epilogue: exact fp32 rescore of top-2, outputs, loss
    const int row = rowbase + tid;
    int ca = rowtab[tid].x, cb = rowtab[tid].y;
    float xr[D];
    {
        const float4* xp = (const float4*)(x + (size_t)row * D);
        #pragma unroll
        for (int i = 0; i < D / 4; i++) {
            float4 v = xp[i];
            xr[4*i] = v.x; xr[4*i+1] = v.y; xr[4*i+2] = v.z; xr[4*i+3] = v.w;
        }
    }
    float da = 0.f, db = 0.f;
    {
        const float* ea = g_et + (size_t)ca * D;
        const float* eb = g_et + (size_t)cb * D;
        #pragma unroll
        for (int d = 0; d < D; d++) {
            da = fmaf(xr[d], ea[d], da);
            db = fmaf(xr[d], eb[d], db);
        }
    }
    float sa = fmaf(-2.f, da, esq_s[ca]);
    float sb = fmaf(-2.f, db, esq_s[cb]);
    int bi = sless(sb, cb, sa, ca) ? cb : ca;

    float ls = 0.f;
    {
        const float4* ep = (const float4*)(g_et + (size_t)bi * D);
        float4* qp = (float4*)(out + OFF_QUANT + (size_t)row * D);
        #pragma unroll
        for (int i = 0; i < D / 4; i++) {
            float4 e = ep[i];
            qp[i] = e;
            float d0 = e.x - xr[4*i],   d1 = e.y - xr[4*i+1];
            float d2 = e.z - xr[4*i+2], d3 = e.w - xr[4*i+3];
            ls = fmaf(d0, d0, ls); ls = fmaf(d1, d1, ls);
            ls = fmaf(d2, d2, ls); ls = fmaf(d3, d3, ls);
        }
    }
    #pragma unroll
    for (int off = 16; off > 0; off >>= 1)
        ls += __shfl_xor_sync(0xFFFFFFFF, ls, off);
    if (lane == 0)   // fixed-point accumulate: order-independent => deterministic
        atomicAdd(&g_loss, (unsigned long long)__float2ll_rn(ls * 16777216.0f));

    out[OFF_IDX + row] = (float)bi;
    out[OFF_ENC + (size_t)row * K + bi] = 1.0f;
}

__global__ void loss_finalize(float* __restrict__ out) {
    out[OFF_LOSS] = (float)((double)g_loss
                  / (16777216.0 * (double)N_ROWS * (double)D));
}

extern "C" void kernel_launch(void* const* d_in, const int* in_sizes, int n_in,
                              void* d_out, int out_size) {
    const float* x   = (const float*)d_in[0];   // [8,4096,64]
    const float* emb = (const float*)d_in[1];   // [64,1024]
    float* out = (float*)d_out;

    cudaFuncSetAttribute(vq_mma, cudaFuncAttributeMaxDynamicSharedMemorySize,
                         SMEM_SZ);
    prep_et<<<(K + 255) / 256, 256>>>(emb);
    prep_frag<<<64, 256>>>(emb);
    vq_mma<<<NBLK, BLK, SMEM_SZ>>>(x, out);
    loss_finalize<<<1, 1>>>(out);
}